// round 4
// baseline (speedup 1.0000x reference)
#include <cuda_runtime.h>
#include <cstdint>

// ---------------- scratch (static device globals; no allocs allowed) ----------------
__device__ __align__(16) float g_Kh [16*4*1024*240];   // [B,H,N,240]
__device__ __align__(16) float g_Vh [16*4*1024*240];   // [B,H,N,240]
__device__ __align__(16) float g_Q  [16*4*1024*240];   // [B,H,N,240] packed at col 0/16/48/112
__device__ __align__(16) float g_S  [16*4*240*240];    // [B,H,240,240] scores -> probs
__device__ __align__(16) float g_ctx[16*1024*960];     // per-scale ctx [B,N,c] concatenated

// head-channel regrouping of emb_all (run boundaries are multiples of 16, so a
// 16-wide k-tile maps to one contiguous gmem run)
__device__ __forceinline__ int head_map(int d, int h) {
    if (d < 16)  return h*16  + d;
    if (d < 48)  return 64  + h*32  + (d-16);
    if (d < 112) return 192 + h*64  + (d-48);
    return 448 + h*128 + (d-112);
}

__device__ __forceinline__ uint32_t f2tf(float x) {
    uint32_t r;
    asm("cvt.rna.tf32.f32 %0, %1;" : "=r"(r) : "f"(x));
    return r;
}

__device__ __forceinline__ void cp16(uint32_t dst, const void* src, bool p) {
    asm volatile("cp.async.ca.shared.global [%0], [%1], 16, %2;\n"
                 :: "r"(dst), "l"(src), "r"(p ? 16 : 0));
}
#define CP_COMMIT() asm volatile("cp.async.commit_group;\n" ::: "memory")
#define CP_WAIT1()  asm volatile("cp.async.wait_group 1;\n" ::: "memory")
#define CP_WAIT0()  asm volatile("cp.async.wait_group 0;\n" ::: "memory")

// ---------------- split-tf32 (3xTF32) tensor-core GEMM, cp.async double-buffered ----
// NT (TN=false): C[m,n] = sum_k A[m*lda+k] * B[n*ldb+k]   (A,B row-major in smem, pad 20)
// TN (TN=true) : C[m,n] = sum_k A[k*lda+m] * B[k*ldb+n]   (k-major in smem, pad 136)
// GATHER: A columns remapped via head_map. CMODE 1: ctx scatter epilogue.
// Block 128x128, K-tile 16, 8 warps, warp tile 64x32, mma.m16n8k8 tf32 x3 passes.
template<bool TN, bool GATHER, int CMODE>
__global__ __launch_bounds__(256, 2) void mma_gemm(
    const float* __restrict__ A, long a_bs, long a_hs, int lda,
    const float* __restrict__ B, long b_bs, long b_hs, int ldb,
    float* __restrict__ C, long c_bs, long c_hs, int ldc,
    int M, int Nn, int Kk)
{
    __shared__ __align__(16) float As[2][2560];  // NT: 128*20 ; TN: 16*136
    __shared__ __align__(16) float Bs[2][2560];

    const int z = blockIdx.z;
    const int b = z >> 2, h = z & 3;
    A += (long)b*a_bs + (long)h*a_hs;
    B += (long)b*b_bs + (long)h*b_hs;
    if (CMODE == 0) C += (long)b*c_bs + (long)h*c_hs;

    const int tid  = threadIdx.x;
    const int warp = tid >> 5, lane = tid & 31;
    const int grp  = lane >> 2, qid = lane & 3;
    const int wm0  = (warp & 1) * 64;
    const int wn0  = (warp >> 1) * 32;
    const int m0 = blockIdx.x * 128, n0 = blockIdx.y * 128;

    const uint32_t sA0 = (uint32_t)__cvta_generic_to_shared(&As[0][0]);
    const uint32_t sB0 = (uint32_t)__cvta_generic_to_shared(&Bs[0][0]);

    float acc[4][4][4];
    #pragma unroll
    for (int i = 0; i < 4; i++)
        #pragma unroll
        for (int j = 0; j < 4; j++)
            #pragma unroll
            for (int r = 0; r < 4; r++) acc[i][j][r] = 0.f;

    auto load_tile = [&](int st, int k0) {
        const uint32_t sA = sA0 + st * 2560 * 4;
        const uint32_t sB = sB0 + st * 2560 * 4;
        if (!TN) {
            const int row = tid >> 1, kq = (tid & 1) * 8;
            {
                const bool p = (m0 + row) < M;
                const int gm = p ? (m0 + row) : 0;
                const float* pa = A + (long)gm*lda + (GATHER ? head_map(k0,h)+kq : k0+kq);
                const uint32_t d = sA + (row*20 + kq)*4;
                cp16(d, pa, p); cp16(d+16, pa+4, p);
            }
            {
                const bool p = (n0 + row) < Nn;
                const int gn = p ? (n0 + row) : 0;
                const float* pb = B + (long)gn*ldb + k0 + kq;
                const uint32_t d = sB + (row*20 + kq)*4;
                cp16(d, pb, p); cp16(d+16, pb+4, p);
            }
        } else {
            const int kr = tid >> 4, q = (tid & 15) * 8;
            {
                const bool p0 = (m0 + q) < M, p1 = (m0 + q + 4) < M;
                const float* pa = A + (long)(k0+kr)*lda + (p0 ? m0 + q : 0);
                const uint32_t d = sA + (kr*136 + q)*4;
                cp16(d, pa, p0); cp16(d+16, p1 ? pa+4 : pa, p1);
            }
            {
                const bool p0 = (n0 + q) < Nn, p1 = (n0 + q + 4) < Nn;
                const float* pb = B + (long)(k0+kr)*ldb + (p0 ? n0 + q : 0);
                const uint32_t d = sB + (kr*136 + q)*4;
                cp16(d, pb, p0); cp16(d+16, p1 ? pb+4 : pb, p1);
            }
        }
    };

    load_tile(0, 0);
    CP_COMMIT();
    int st = 0;

    for (int k0 = 0; k0 < Kk; k0 += 16) {
        if (k0 + 16 < Kk) {
            load_tile(st ^ 1, k0 + 16);
            CP_COMMIT();
            CP_WAIT1();   // current tile's group fully retired (FIFO)
        } else {
            CP_WAIT0();   // last tile: drain everything
        }
        __syncthreads();

        const float* cA = As[st];
        const float* cB = Bs[st];

        #pragma unroll
        for (int ks = 0; ks < 2; ks++) {
            const int kb = ks * 8;
            uint32_t ahi[4][4], alo[4][4], bhi[4][2], blo[4][2];
            #pragma unroll
            for (int i = 0; i < 4; i++) {
                const int mr = wm0 + i*16 + grp;
                #pragma unroll
                for (int s = 0; s < 4; s++) {
                    const int kk = kb + qid + ((s >> 1) << 2);
                    const int mm = mr + ((s & 1) << 3);
                    const float x = TN ? cA[kk*136 + mm] : cA[mm*20 + kk];
                    const uint32_t hv = f2tf(x);
                    ahi[i][s] = hv;
                    alo[i][s] = f2tf(x - __uint_as_float(hv));
                }
            }
            #pragma unroll
            for (int j = 0; j < 4; j++) {
                const int nc = wn0 + j*8 + grp;
                #pragma unroll
                for (int s = 0; s < 2; s++) {
                    const int kk = kb + qid + s*4;
                    const float x = TN ? cB[kk*136 + nc] : cB[nc*20 + kk];
                    const uint32_t hv = f2tf(x);
                    bhi[j][s] = hv;
                    blo[j][s] = f2tf(x - __uint_as_float(hv));
                }
            }
            #pragma unroll
            for (int i = 0; i < 4; i++)
                #pragma unroll
                for (int j = 0; j < 4; j++) {
                    asm volatile(
                        "mma.sync.aligned.m16n8k8.row.col.f32.tf32.tf32.f32 "
                        "{%0,%1,%2,%3}, {%4,%5,%6,%7}, {%8,%9}, {%0,%1,%2,%3};\n"
                        : "+f"(acc[i][j][0]), "+f"(acc[i][j][1]),
                          "+f"(acc[i][j][2]), "+f"(acc[i][j][3])
                        : "r"(ahi[i][0]), "r"(ahi[i][1]), "r"(ahi[i][2]), "r"(ahi[i][3]),
                          "r"(bhi[j][0]), "r"(bhi[j][1]));
                    asm volatile(
                        "mma.sync.aligned.m16n8k8.row.col.f32.tf32.tf32.f32 "
                        "{%0,%1,%2,%3}, {%4,%5,%6,%7}, {%8,%9}, {%0,%1,%2,%3};\n"
                        : "+f"(acc[i][j][0]), "+f"(acc[i][j][1]),
                          "+f"(acc[i][j][2]), "+f"(acc[i][j][3])
                        : "r"(ahi[i][0]), "r"(ahi[i][1]), "r"(ahi[i][2]), "r"(ahi[i][3]),
                          "r"(blo[j][0]), "r"(blo[j][1]));
                    asm volatile(
                        "mma.sync.aligned.m16n8k8.row.col.f32.tf32.tf32.f32 "
                        "{%0,%1,%2,%3}, {%4,%5,%6,%7}, {%8,%9}, {%0,%1,%2,%3};\n"
                        : "+f"(acc[i][j][0]), "+f"(acc[i][j][1]),
                          "+f"(acc[i][j][2]), "+f"(acc[i][j][3])
                        : "r"(alo[i][0]), "r"(alo[i][1]), "r"(alo[i][2]), "r"(alo[i][3]),
                          "r"(bhi[j][0]), "r"(bhi[j][1]));
                }
        }
        __syncthreads();
        st ^= 1;
    }

    // epilogue
    #pragma unroll
    for (int i = 0; i < 4; i++) {
        #pragma unroll
        for (int j = 0; j < 4; j++) {
            const int mA = m0 + wm0 + i*16 + grp;
            const int nA = n0 + wn0 + j*8 + 2*qid;
            #pragma unroll
            for (int half = 0; half < 2; half++) {
                const int m = mA + half*8;
                const float c0 = acc[i][j][half*2+0];
                const float c1 = acc[i][j][half*2+1];
                if (CMODE == 0) {
                    if (m < M && nA < Nn) {
                        float2 v = make_float2(c0, c1);
                        *(float2*)&C[(long)m*ldc + nA] = v;
                    }
                } else {
                    if (m < M && nA < Nn) {
                        int s, doff;
                        if      (m < 16)  { s = 0; doff = m; }
                        else if (m < 48)  { s = 1; doff = m - 16; }
                        else if (m < 112) { s = 2; doff = m - 48; }
                        else              { s = 3; doff = m - 112; }
                        const long ctxoff[4] = {0, 16384L*64, 16384L*192, 16384L*448};
                        const int  chc[4]    = {64, 128, 256, 512};
                        long base = ctxoff[s] + (long)doff*4 + h;
                        C[base + ((long)(b*1024 + nA  ))*chc[s]] = c0;
                        C[base + ((long)(b*1024 + nA+1))*chc[s]] = c1;
                    }
                }
            }
        }
    }
}

// ---------------- instance-norm (per b,h,scale over [d,240]) + row softmax ----------------
__global__ __launch_bounds__(256) void norm_softmax_k(float* __restrict__ S)
{
    const int roff[4] = {0, 16, 48, 112};
    const int dsz[4]  = {16, 32, 64, 128};
    const int s  = blockIdx.x;
    const int bh = blockIdx.y;
    float* Sp = S + (long)bh*240*240 + (long)roff[s]*240;
    const int d = dsz[s];
    const int cnt = d * 240;
    const float alpha = 0.0322748612f;  // 1/sqrt(960)
    const int tid = threadIdx.x;

    float lsum = 0.f, lsq = 0.f;
    for (int i = tid; i < cnt; i += 256) {
        float x = Sp[i] * alpha;
        lsum += x; lsq += x*x;
    }
    __shared__ float r1[256], r2[256];
    r1[tid] = lsum; r2[tid] = lsq;
    __syncthreads();
    for (int o = 128; o; o >>= 1) {
        if (tid < o) { r1[tid] += r1[tid+o]; r2[tid] += r2[tid+o]; }
        __syncthreads();
    }
    const float mean = r1[0] / cnt;
    const float var  = r2[0] / cnt - mean*mean;
    const float rstd = rsqrtf(var + 1e-5f);

    const int w = tid >> 5, lane = tid & 31;
    for (int r = w; r < d; r += 8) {
        float zv[8];
        float mx = -1e30f;
        #pragma unroll
        for (int j = 0; j < 8; j++) {
            int c = lane + 32*j;
            if (c < 240) {
                float x = (Sp[r*240 + c]*alpha - mean) * rstd;
                zv[j] = x; mx = fmaxf(mx, x);
            } else zv[j] = -1e30f;
        }
        for (int o = 16; o; o >>= 1) mx = fmaxf(mx, __shfl_xor_sync(0xffffffffu, mx, o));
        float ssum = 0.f;
        #pragma unroll
        for (int j = 0; j < 8; j++) {
            int c = lane + 32*j;
            if (c < 240) { float e = __expf(zv[j] - mx); zv[j] = e; ssum += e; }
        }
        for (int o = 16; o; o >>= 1) ssum += __shfl_xor_sync(0xffffffffu, ssum, o);
        float inv = __frcp_rn(ssum);
        #pragma unroll
        for (int j = 0; j < 8; j++) {
            int c = lane + 32*j;
            if (c < 240) Sp[r*240 + c] = zv[j] * inv;
        }
    }
}

// ---------------- launch ----------------
extern "C" void kernel_launch(void* const* d_in, const int* in_sizes, int n_in,
                              void* d_out, int out_size)
{
    const float* emb[4]  = {(const float*)d_in[0], (const float*)d_in[1],
                            (const float*)d_in[2], (const float*)d_in[3]};
    const float* emb_all = (const float*)d_in[4];
    const float* Wq[4]   = {(const float*)d_in[5], (const float*)d_in[6],
                            (const float*)d_in[7], (const float*)d_in[8]};
    const float* Wk      = (const float*)d_in[9];
    const float* Wv      = (const float*)d_in[10];
    const float* Wo[4]   = {(const float*)d_in[11], (const float*)d_in[12],
                            (const float*)d_in[13], (const float*)d_in[14]};
    float* out = (float*)d_out;

    float *Kh, *Vh, *Q, *S, *ctx;
    cudaGetSymbolAddress((void**)&Kh,  g_Kh);
    cudaGetSymbolAddress((void**)&Vh,  g_Vh);
    cudaGetSymbolAddress((void**)&Q,   g_Q);
    cudaGetSymbolAddress((void**)&S,   g_S);
    cudaGetSymbolAddress((void**)&ctx, g_ctx);

    const int  CHs[4]  = {64, 128, 256, 512};
    const int  qoff[4] = {0, 16, 48, 112};
    const long boff[4] = {0, 16384L*64, 16384L*192, 16384L*448};

    const long st = 4L*1024*240;
    const long sh = 1024L*240;
    const long Sb = 4L*240*240;
    const long Sh = 240L*240;

    // 1) K/V projections (gathered A from emb_all)
    mma_gemm<false, true, 0><<<dim3(8, 2, 64), 256>>>(
        emb_all, 1024L*960, 0, 960,  Wk, 0, 0, 240,  Kh, st, sh, 240,  1024, 240, 240);
    mma_gemm<false, true, 0><<<dim3(8, 2, 64), 256>>>(
        emb_all, 1024L*960, 0, 960,  Wv, 0, 0, 240,  Vh, st, sh, 240,  1024, 240, 240);

    // 2) Q projections (4 scales) into packed g_Q columns
    for (int sc = 0; sc < 4; sc++) {
        int c = CHs[sc], d = c / 4;
        mma_gemm<false, false, 0><<<dim3(8, 1, 64), 256>>>(
            emb[sc], 1024L*c, d, c,  Wq[sc], 0, (long)d*d, d,
            Q + qoff[sc], st, sh, 240,  1024, d, d);
    }

    // 3) scores = Q^T K over N=1024 (TN)
    mma_gemm<true, false, 0><<<dim3(2, 2, 64), 256>>>(
        Q, st, sh, 240,  Kh, st, sh, 240,  S, Sb, Sh, 240,  240, 240, 1024);

    // 4) instance-norm + softmax (in place)
    norm_softmax_k<<<dim3(4, 64), 256>>>(S);

    // 5) ctx = probs @ V^T, scattered into [B,N,c] per-scale layout
    mma_gemm<false, false, 1><<<dim3(2, 8, 64), 256>>>(
        S, Sb, Sh, 240,  Vh, st, sh, 240,  ctx, 0, 0, 0,  240, 1024, 240);

    // 6) output projections per scale
    for (int sc = 0; sc < 4; sc++) {
        int c = CHs[sc];
        int nb = c / 128; if (nb < 1) nb = 1;
        mma_gemm<false, false, 0><<<dim3(128, nb, 1), 256>>>(
            ctx + boff[sc], 0, 0, c,  Wo[sc], 0, 0, c,
            out + boff[sc], 0, 0, c,  16384, c, c);
    }
}